// round 1
// baseline (speedup 1.0000x reference)
#include <cuda_runtime.h>
#include <cuda_bf16.h>
#include <math.h>

// Problem constants
#define BATCH 128
#define CTX 64
#define IN_SIZE 128
#define HID 128
#define NSLOT 9            // NUM_SLOTS + 1
#define KSLICES 19         // 9 time + 9 dist + 1 hidden
#define KTOT (KSLICES * 128)   // 2432

// Scratch (allocation-free rule: __device__ globals)
__device__ float g_XaggT[KTOT * BATCH];   // [k][b], k-major, batch minor (coalesced for K2)
__device__ float g_outpre[BATCH * HID];   // fp32 pre-sigmoid accumulator

// ---------------------------------------------------------------------------
// K1: per-batch slot aggregation.
//   grid = BATCH blocks, 128 threads (thread = input dim)
//   - builds acc[18][128] in smem (each thread owns its dim column: no conflicts,
//     no syncs needed on acc)
//   - writes XaggT[(slot*128+dim)][b] (transposed for K2 coalescing)
//   - copies h transposed into XaggT rows 2304..2431
//   - zeroes g_outpre row b
//   - runtime-sniffs mask dtype (int32 vs packed bool bytes)
// ---------------------------------------------------------------------------
__global__ __launch_bounds__(128, 8)
void k1_aggregate(const float* __restrict__ x,         // [B][CTX][IN]
                  const int* __restrict__ timec,       // [B][CTX]
                  const int* __restrict__ distc,       // [B][CTX]
                  const void* __restrict__ maskp,      // [B][CTX] int32 OR bytes
                  const float* __restrict__ h)         // [B][HID]
{
    __shared__ float acc[18 * 128];
    __shared__ int s_time[CTX];
    __shared__ int s_dist[CTX];
    __shared__ int s_flag;       // 1 -> mask stored as bytes
    __shared__ float s_w[CTX];   // 0.5 * mask

    const int b = blockIdx.x;
    const int tid = threadIdx.x;

    if (tid == 0) s_flag = 0;
    #pragma unroll
    for (int i = tid; i < 18 * 128; i += 128) acc[i] = 0.0f;
    __syncthreads();

    // --- mask dtype sniff: first 2048 words are in-bounds under BOTH layouts
    // (int32 layout: 8192 ints; byte layout: 8192 bytes == 2048 ints).
    {
        const unsigned int* m32 = (const unsigned int*)maskp;
        int bad = 0;
        #pragma unroll
        for (int i = tid; i < 2048; i += 128)
            bad |= (m32[i] > 1u);
        if (bad) atomicOr(&s_flag, 1);
    }
    __syncthreads();
    const int byte_layout = s_flag;

    // --- stage per-ctx indices + weights in smem
    if (tid < CTX) {
        int c = tid;
        s_time[c] = timec[b * CTX + c];
        s_dist[c] = distc[b * CTX + c];
        int m;
        if (byte_layout) m = ((const unsigned char*)maskp)[b * CTX + c] != 0;
        else             m = ((const int*)maskp)[b * CTX + c] != 0;
        s_w[c] = m ? 0.5f : 0.0f;
    }
    // zero out_pre row while we're here
    g_outpre[b * HID + tid] = 0.0f;
    __syncthreads();

    // --- accumulate: each thread owns column `tid` of every slot accumulator
    const float* xrow = x + (size_t)b * CTX * IN_SIZE + tid;
    #pragma unroll 4
    for (int c = 0; c < CTX; c++) {
        float xi = xrow[c * IN_SIZE];
        float w  = s_w[c];
        float v  = w * xi;
        int t = s_time[c];
        int d = s_dist[c];
        acc[t * 128 + tid]       += v;
        acc[(9 + d) * 128 + tid] += v;
    }

    // --- write transposed aggregate (no sync needed: thread-private columns)
    #pragma unroll
    for (int s = 0; s < 18; s++) {
        g_XaggT[(size_t)(s * 128 + tid) * BATCH + b] = acc[s * 128 + tid];
    }
    // hidden block: A slice 18 is h
    g_XaggT[(size_t)(2304 + tid) * BATCH + b] = h[b * HID + tid];
}

// ---------------------------------------------------------------------------
// K2: split-K GEMM  out_pre[b][j] += sum_k A[b][k] * W[k][j]
//   grid = (8 n-tiles, 19 K-slices), 128 threads (thread = batch row)
//   A loads coalesced from XaggT[k][b]; W tile (128x16) broadcast from smem.
// ---------------------------------------------------------------------------
__global__ __launch_bounds__(128, 8)
void k2_gemm(const float* __restrict__ tw,   // [9][128][128]
             const float* __restrict__ dw,   // [9][128][128]
             const float* __restrict__ hw)   // [128][128]
{
    const int ntile = blockIdx.x;        // 0..7 -> cols ntile*16 .. +16
    const int ks    = blockIdx.y;        // 0..18
    const int tid   = threadIdx.x;       // batch row

    const float* Wsrc;
    if (ks < 9)       Wsrc = tw + (size_t)ks * 128 * 128;
    else if (ks < 18) Wsrc = dw + (size_t)(ks - 9) * 128 * 128;
    else              Wsrc = hw;

    __shared__ float Ws[128 * 16];
    const int j0 = ntile * 16;
    #pragma unroll
    for (int i = tid; i < 128 * 16; i += 128) {
        int k = i >> 4;
        int j = i & 15;
        Ws[i] = Wsrc[k * 128 + j0 + j];
    }
    __syncthreads();

    float accv[16];
    #pragma unroll
    for (int j = 0; j < 16; j++) accv[j] = 0.0f;

    const float* Acol = g_XaggT + (size_t)ks * 128 * BATCH + tid;
    #pragma unroll 4
    for (int k = 0; k < 128; k++) {
        float a = Acol[(size_t)k * BATCH];
        const float4* wrow = (const float4*)(Ws + k * 16);
        #pragma unroll
        for (int q = 0; q < 4; q++) {
            float4 w = wrow[q];
            accv[q * 4 + 0] += a * w.x;
            accv[q * 4 + 1] += a * w.y;
            accv[q * 4 + 2] += a * w.z;
            accv[q * 4 + 3] += a * w.w;
        }
    }

    float* dst = g_outpre + tid * HID + j0;
    #pragma unroll
    for (int j = 0; j < 16; j++)
        atomicAdd(&dst[j], accv[j]);
}

// ---------------------------------------------------------------------------
// K3: sigmoid epilogue
// ---------------------------------------------------------------------------
__global__ void k3_sigmoid(float* __restrict__ out)
{
    int i = blockIdx.x * blockDim.x + threadIdx.x;
    if (i < BATCH * HID) {
        float v = g_outpre[i];
        out[i] = 1.0f / (1.0f + expf(-v));
    }
}

// ---------------------------------------------------------------------------
extern "C" void kernel_launch(void* const* d_in, const int* in_sizes, int n_in,
                              void* d_out, int out_size)
{
    const float* x    = (const float*)d_in[0];   // x_context
    const int*   tc   = (const int*)  d_in[1];   // time_context
    const int*   dc   = (const int*)  d_in[2];   // dist_context
    const void*  mask = (const void*) d_in[3];   // context_mask (dtype sniffed)
    const float* h    = (const float*)d_in[4];   // h
    const float* tw   = (const float*)d_in[5];   // time_weights
    const float* dw   = (const float*)d_in[6];   // dist_weights
    const float* hw   = (const float*)d_in[7];   // hidden_weights
    float* out = (float*)d_out;

    k1_aggregate<<<BATCH, 128>>>(x, tc, dc, mask, h);
    dim3 g2(8, KSLICES);
    k2_gemm<<<g2, 128>>>(tw, dw, hw);
    k3_sigmoid<<<(BATCH * HID + 255) / 256, 256>>>(out);
}

// round 2
// speedup vs baseline: 1.4656x; 1.4656x over previous
#include <cuda_runtime.h>
#include <math.h>

#define BATCH 128
#define CTX 64
#define HID 128
#define KSLICES 19          // 9 time + 9 dist + 1 hidden
#define KTOT (KSLICES*128)  // 2432

typedef unsigned long long u64;

// Scratch (__device__ globals: allocation-free rule)
__device__ float g_XaggT[KTOT * BATCH];            // [k][b]  (coalesced A for K2)
__device__ float g_gpart[KSLICES * BATCH * HID];   // per-slice GEMM partials

// ---- packed f32x2 helpers (Blackwell FFMA2) --------------------------------
__device__ __forceinline__ u64 pack2(float v) {
    u64 r; asm("mov.b64 %0, {%1, %1};" : "=l"(r) : "f"(v)); return r;
}
__device__ __forceinline__ void ffma2(u64& d, u64 a, u64 b) {
    asm("fma.rn.f32x2 %0, %1, %2, %0;" : "+l"(d) : "l"(a), "l"(b));
}
__device__ __forceinline__ u64 fadd2(u64 a, u64 b) {
    u64 r; asm("add.rn.f32x2 %0, %1, %2;" : "=l"(r) : "l"(a), "l"(b)); return r;
}

// ---------------------------------------------------------------------------
// K1: per-batch slot aggregation as a tiny GEMM  acc[18][128] = sel[18][64] @ x[64][128]
//   grid = 128 (batch), 128 threads = 4 ctx-groups x 32 dim-quads.
//   Register accumulators (36 x f32x2), sel broadcast from smem. No RMW chains.
// ---------------------------------------------------------------------------
__global__ __launch_bounds__(128, 1)
void k1_aggregate(const float* __restrict__ x,     // [B][CTX][128]
                  const int* __restrict__ timec,   // [B][CTX]
                  const int* __restrict__ distc,   // [B][CTX]
                  const void* __restrict__ maskp,  // [B][CTX] int32 OR bytes
                  const float* __restrict__ h)     // [B][128]
{
    __shared__ float sel[CTX][18];     // 4.6KB
    __shared__ float red[4][18 * 128]; // 36.9KB partials
    __shared__ int s_flag;

    const int b = blockIdx.x;
    const int tid = threadIdx.x;

    if (tid == 0) s_flag = 0;
    __syncthreads();

    // mask dtype sniff: first 2048 words are in-bounds under both layouts
    {
        const unsigned int* m32 = (const unsigned int*)maskp;
        int bad = 0;
        #pragma unroll
        for (int i = tid; i < 2048; i += 128) bad |= (m32[i] > 1u);
        if (bad) atomicOr(&s_flag, 1);
    }
    __syncthreads();
    const int byte_layout = s_flag;

    // sel[c][s] = (slot==s) ? 0.5*mask : 0   (thread = (c, time/dist half))
    {
        int c  = tid & 63;
        int hf = tid >> 6;
        int t = timec[b * CTX + c];
        int d = distc[b * CTX + c];
        int m;
        if (byte_layout) m = ((const unsigned char*)maskp)[b * CTX + c] != 0;
        else             m = ((const int*)maskp)[b * CTX + c] != 0;
        float w = m ? 0.5f : 0.0f;
        int idx = hf ? d : t;
        #pragma unroll
        for (int s = 0; s < 9; s++)
            sel[c][hf * 9 + s] = (idx == s) ? w : 0.0f;
    }
    __syncthreads();

    const int g = tid >> 5;   // ctx group: c in [16g, 16g+16)
    const int q = tid & 31;   // dim quad:  dims 4q..4q+3

    u64 acc[36];              // [s][pair] packed f32x2
    #pragma unroll
    for (int i = 0; i < 36; i++) acc[i] = 0ull;

    const float* xb = x + (size_t)b * CTX * 128 + q * 4;
    #pragma unroll 2
    for (int cc = 0; cc < 16; cc++) {
        int c = g * 16 + cc;
        double2 xv = *(const double2*)(xb + c * 128);   // LDG.128: 4 dims
        u64 x0 = __double_as_longlong(xv.x);
        u64 x1 = __double_as_longlong(xv.y);
        #pragma unroll
        for (int s = 0; s < 18; s++) {
            u64 s2 = pack2(sel[c][s]);                  // broadcast LDS
            ffma2(acc[2 * s],     s2, x0);
            ffma2(acc[2 * s + 1], s2, x1);
        }
    }

    // write per-group partials (STS.128, conflict-free)
    #pragma unroll
    for (int s = 0; s < 18; s++) {
        ulonglong2 v; v.x = acc[2 * s]; v.y = acc[2 * s + 1];
        *(ulonglong2*)&red[g][s * 128 + q * 4] = v;
    }
    __syncthreads();

    // reduce 4 partials and scatter into transposed aggregate [k][b]
    #pragma unroll
    for (int s = 0; s < 18; s++) {
        float v = red[0][s * 128 + tid] + red[1][s * 128 + tid]
                + red[2][s * 128 + tid] + red[3][s * 128 + tid];
        g_XaggT[(size_t)(s * 128 + tid) * BATCH + b] = v;
    }
    // hidden slice (rows 2304..2431) = h transposed
    g_XaggT[(size_t)(2304 + tid) * BATCH + b] = h[b * HID + tid];
}

// ---------------------------------------------------------------------------
// K2: per-slice GEMM partial  g_gpart[ks][b][j0..j0+16] = A_ks[b][:] @ W_ks[:, j0..]
//   grid = (8 n-tiles, 19 slices), 256 threads = 2 k-halves x 128 batch rows.
//   f32x2 FFMA, W tile broadcast from smem via LDS.128, coalesced A loads.
// ---------------------------------------------------------------------------
__global__ __launch_bounds__(256, 1)
void k2_gemm(const float* __restrict__ tw,   // [9][128][128]
             const float* __restrict__ dw,   // [9][128][128]
             const float* __restrict__ hw)   // [128][128]
{
    const int ntile = blockIdx.x;       // cols j0 = 16*ntile
    const int ks    = blockIdx.y;       // K slice
    const int tid   = threadIdx.x;
    const int half  = tid >> 7;         // k-split half
    const int row   = tid & 127;        // batch row

    const float* Wsrc;
    if (ks < 9)       Wsrc = tw + (size_t)ks * 16384;
    else if (ks < 18) Wsrc = dw + (size_t)(ks - 9) * 16384;
    else              Wsrc = hw;

    __shared__ float Ws[128 * 16];      // 8KB W tile [k][16]
    __shared__ u64   Cs[128 * 8];       // 8KB half-1 partials

    const int j0 = ntile * 16;
    {
        // stage W: each thread loads 8 consecutive floats of one k-row
        int k = tid >> 1, off = (tid & 1) * 8;
        const float4* src = (const float4*)(Wsrc + k * 128 + j0 + off);
        float4* dst = (float4*)(Ws + k * 16 + off);
        dst[0] = src[0];
        dst[1] = src[1];
    }
    __syncthreads();

    u64 acc[8];
    #pragma unroll
    for (int i = 0; i < 8; i++) acc[i] = 0ull;

    const float* Acol = g_XaggT + ((size_t)ks * 128 + half * 64) * BATCH + row;
    const float* Wrow = Ws + half * 64 * 16;

    #pragma unroll 4
    for (int k = 0; k < 64; k++) {
        u64 a2 = pack2(Acol[(size_t)k * BATCH]);        // coalesced across rows
        const double2* w = (const double2*)(Wrow + k * 16);
        double2 w0 = w[0], w1 = w[1], w2 = w[2], w3 = w[3];   // 4x LDS.128 broadcast
        ffma2(acc[0], a2, __double_as_longlong(w0.x));
        ffma2(acc[1], a2, __double_as_longlong(w0.y));
        ffma2(acc[2], a2, __double_as_longlong(w1.x));
        ffma2(acc[3], a2, __double_as_longlong(w1.y));
        ffma2(acc[4], a2, __double_as_longlong(w2.x));
        ffma2(acc[5], a2, __double_as_longlong(w2.y));
        ffma2(acc[6], a2, __double_as_longlong(w3.x));
        ffma2(acc[7], a2, __double_as_longlong(w3.y));
    }

    if (half) {
        u64* c = Cs + row * 8;
        #pragma unroll
        for (int i = 0; i < 8; i++) c[i] = acc[i];
    }
    __syncthreads();
    if (!half) {
        const u64* c = Cs + row * 8;
        u64* dst = (u64*)(g_gpart + ((size_t)ks * BATCH + row) * HID + j0);
        #pragma unroll
        for (int i = 0; i < 8; i++) dst[i] = fadd2(acc[i], c[i]);
    }
}

// ---------------------------------------------------------------------------
// K3: fold 19 slice partials + sigmoid (coalesced, high MLP)
// ---------------------------------------------------------------------------
__global__ void k3_sigmoid(float* __restrict__ out)
{
    int i = blockIdx.x * blockDim.x + threadIdx.x;   // 16384 threads
    float v = 0.0f;
    #pragma unroll
    for (int ks = 0; ks < KSLICES; ks++)
        v += g_gpart[ks * (BATCH * HID) + i];
    out[i] = 1.0f / (1.0f + expf(-v));
}

// ---------------------------------------------------------------------------
extern "C" void kernel_launch(void* const* d_in, const int* in_sizes, int n_in,
                              void* d_out, int out_size)
{
    const float* x    = (const float*)d_in[0];
    const int*   tc   = (const int*)  d_in[1];
    const int*   dc   = (const int*)  d_in[2];
    const void*  mask = (const void*) d_in[3];
    const float* h    = (const float*)d_in[4];
    const float* tw   = (const float*)d_in[5];
    const float* dw   = (const float*)d_in[6];
    const float* hw   = (const float*)d_in[7];
    float* out = (float*)d_out;

    k1_aggregate<<<BATCH, 128>>>(x, tc, dc, mask, h);
    dim3 g2(8, KSLICES);
    k2_gemm<<<g2, 256>>>(tw, dw, hw);
    k3_sigmoid<<<(BATCH * HID + 255) / 256, 256>>>(out);
}

// round 4
// speedup vs baseline: 1.4977x; 1.0218x over previous
#include <cuda_runtime.h>
#include <math.h>

#define BATCH 128
#define CTX 64
#define HID 128
#define KSLICES 19          // 9 time + 9 dist + 1 hidden
#define KTOT (KSLICES*128)  // 2432

typedef unsigned long long u64;

// Scratch (__device__ globals: allocation-free rule)
__device__ float g_Xagg[BATCH * KTOT];             // [b][k] row-major (coalesced K1 stores)
__device__ float g_gpart[KSLICES * BATCH * HID];   // per-slice GEMM partials

// ---- packed f32x2 helpers --------------------------------------------------
__device__ __forceinline__ u64 pack2(float v) {
    u64 r; asm("mov.b64 %0, {%1, %1};" : "=l"(r) : "f"(v)); return r;
}
__device__ __forceinline__ void ffma2(u64& d, u64 a, u64 b) {
    asm("fma.rn.f32x2 %0, %1, %2, %0;" : "+l"(d) : "l"(a), "l"(b));
}
__device__ __forceinline__ u64 fadd2(u64 a, u64 b) {
    u64 r; asm("add.rn.f32x2 %0, %1, %2;" : "=l"(r) : "l"(a), "l"(b)); return r;
}

// ---------------------------------------------------------------------------
// K1: per-batch slot aggregation  acc[18][128] = sel[18][64] @ x[64][128]
//   grid = 128 (batch), 256 threads = 4 ctx-groups x 64 dim-pairs (8 warps).
//   smem: sel2 9.2KB + red[4] 36.9KB = 46.1KB (< 48KB static limit).
// ---------------------------------------------------------------------------
__global__ __launch_bounds__(256, 1)
void k1_aggregate(const float* __restrict__ x,     // [B][CTX][128]
                  const int* __restrict__ timec,   // [B][CTX]
                  const int* __restrict__ distc,   // [B][CTX]
                  const void* __restrict__ maskp,  // [B][CTX] int32 OR bytes
                  const float* __restrict__ h)     // [B][128]
{
    __shared__ u64   sel2[CTX][18];     // 9216B  (w,w) packed pairs
    __shared__ float red[4][18 * 128];  // 36864B per-group partials
    __shared__ int   s_flag;

    const int b = blockIdx.x;
    const int tid = threadIdx.x;

    if (tid == 0) s_flag = 0;
    __syncthreads();

    // mask dtype sniff: first 2048 words in-bounds under both layouts
    {
        const unsigned int* m32 = (const unsigned int*)maskp;
        int bad = 0;
        #pragma unroll
        for (int i = tid; i < 2048; i += 256) bad |= (m32[i] > 1u);
        if (bad) atomicOr(&s_flag, 1);
    }
    __syncthreads();
    const int byte_layout = s_flag;

    // sel2[c][s] = (slot==s) ? (0.5*mask, 0.5*mask) : (0,0)
    if (tid < 128) {
        int c  = tid & 63;
        int hf = tid >> 6;
        int t = timec[b * CTX + c];
        int d = distc[b * CTX + c];
        int m;
        if (byte_layout) m = ((const unsigned char*)maskp)[b * CTX + c] != 0;
        else             m = ((const int*)maskp)[b * CTX + c] != 0;
        float w = m ? 0.5f : 0.0f;
        int idx = hf ? d : t;
        u64 wp = pack2(w);
        #pragma unroll
        for (int s = 0; s < 9; s++)
            sel2[c][hf * 9 + s] = (idx == s) ? wp : 0ull;
    }
    __syncthreads();

    const int g = tid >> 6;   // ctx group: c in [16g, 16g+16)
    const int q = tid & 63;   // dim pair:  dims 2q, 2q+1

    // front-batched x loads (16 independent LDG.64, coalesced 256B/warp request)
    u64 xv[16];
    {
        const float* xb = x + (size_t)b * CTX * 128 + q * 2;
        #pragma unroll
        for (int cc = 0; cc < 16; cc++)
            xv[cc] = *(const u64*)(xb + (g * 16 + cc) * 128);
    }

    u64 acc[18];
    #pragma unroll
    for (int s = 0; s < 18; s++) acc[s] = 0ull;

    #pragma unroll
    for (int cc = 0; cc < 16; cc++) {
        int c = g * 16 + cc;
        u64 xc = xv[cc];
        #pragma unroll
        for (int s = 0; s < 18; s++)
            ffma2(acc[s], sel2[c][s], xc);     // LDS.64 broadcast + FFMA2
    }

    // per-group partials (STS.64, conflict-free: lanes -> consecutive dims)
    #pragma unroll
    for (int s = 0; s < 18; s++)
        *(u64*)&red[g][s * 128 + q * 2] = acc[s];
    __syncthreads();

    // fold 4 groups, write coalesced row g_Xagg[b][i]
    float* dstrow = g_Xagg + (size_t)b * KTOT;
    #pragma unroll
    for (int i = tid; i < 18 * 128; i += 256) {
        float v = red[0][i] + red[1][i] + red[2][i] + red[3][i];
        dstrow[i] = v;
    }
    // hidden slice: rows 2304..2431 = h[b][:]
    if (tid < 128) dstrow[2304 + tid] = h[b * HID + tid];
}

// ---------------------------------------------------------------------------
// K2: per-slice GEMM partial  g_gpart[ks][b][j0..j0+16) = A_ks[b][:] @ W_ks[:, j0..)
//   grid = (8 n-tiles, 19 slices), 256 threads = 2 k-halves x 128 batch rows.
//   A staged in two 32KB XOR-swizzled chunks (conflict-free STS and LDS,
//   pitch 128, no pad). Half-1 partial buffer aliases As after the mainloop.
//   smem total: 32KB + 8KB = 40KB.
// ---------------------------------------------------------------------------
__global__ __launch_bounds__(256, 1)
void k2_gemm(const float* __restrict__ tw,   // [9][128][128]
             const float* __restrict__ dw,   // [9][128][128]
             const float* __restrict__ hw)   // [128][128]
{
    const int ntile = blockIdx.x;       // cols j0 = 16*ntile
    const int ks    = blockIdx.y;       // K slice
    const int tid   = threadIdx.x;
    const int half  = tid >> 7;         // k-split half (k 0-63 / 64-127)
    const int row   = tid & 127;        // batch row

    const float* Wsrc;
    if (ks < 9)       Wsrc = tw + (size_t)ks * 16384;
    else if (ks < 18) Wsrc = dw + (size_t)(ks - 9) * 16384;
    else              Wsrc = hw;

    __shared__ __align__(16) float As[64 * 128];  // 32KB: [kf][b^kk] swizzled chunk
    __shared__ float Ws[128 * 16];                // 8KB:  W[k][j]

    const int j0 = ntile * 16;
    {
        // W tile: thread -> one (k, 8-col chunk); coalesced LDG, conflict-free STS
        int k = tid >> 1, off = (tid & 1) * 8;
        const float4* src = (const float4*)(Wsrc + k * 128 + j0 + off);
        float4* dst = (float4*)(Ws + k * 16 + off);
        dst[0] = src[0];
        dst[1] = src[1];
    }

    u64 acc[8];
    #pragma unroll
    for (int i = 0; i < 8; i++) acc[i] = 0ull;

    const float* Abase = g_Xagg + ks * 128;

    #pragma unroll
    for (int c = 0; c < 2; c++) {
        __syncthreads();
        // stage chunk: kf = h*32+kk covers k = h*64 + c*32 + kk for both halves
        #pragma unroll
        for (int i = 0; i < 32; i++) {
            int idx = i * 256 + tid;
            int kf = idx & 63;          // lanes -> consecutive k (coalesced LDG)
            int bb = idx >> 6;
            int hh = kf >> 5, kk = kf & 31;
            int kglob = hh * 64 + c * 32 + kk;
            As[kf * 128 + (bb ^ kk)] = Abase[(size_t)bb * KTOT + kglob];
        }
        __syncthreads();

        const float* Arow = As + half * 32 * 128;
        const float* Wrow = Ws + (half * 64 + c * 32) * 16;
        #pragma unroll 8
        for (int kk = 0; kk < 32; kk++) {
            u64 a2 = pack2(Arow[kk * 128 + (row ^ kk)]);       // LDS.32 conflict-free
            const double2* w = (const double2*)(Wrow + kk * 16);
            double2 w0 = w[0], w1 = w[1], w2 = w[2], w3 = w[3]; // LDS.128 broadcast
            ffma2(acc[0], a2, __double_as_longlong(w0.x));
            ffma2(acc[1], a2, __double_as_longlong(w0.y));
            ffma2(acc[2], a2, __double_as_longlong(w1.x));
            ffma2(acc[3], a2, __double_as_longlong(w1.y));
            ffma2(acc[4], a2, __double_as_longlong(w2.x));
            ffma2(acc[5], a2, __double_as_longlong(w2.y));
            ffma2(acc[6], a2, __double_as_longlong(w3.x));
            ffma2(acc[7], a2, __double_as_longlong(w3.y));
        }
    }

    // combine halves: Cs aliases As (mainloop done, sync-separated)
    __syncthreads();
    u64* Cs = (u64*)As;
    if (half) {
        u64* cdst = Cs + row * 8;
        #pragma unroll
        for (int i = 0; i < 8; i++) cdst[i] = acc[i];
    }
    __syncthreads();
    if (!half) {
        const u64* csrc = Cs + row * 8;
        u64* dst = (u64*)(g_gpart + ((size_t)ks * BATCH + row) * HID + j0);
        #pragma unroll
        for (int i = 0; i < 8; i++) dst[i] = fadd2(acc[i], csrc[i]);
    }
}

// ---------------------------------------------------------------------------
// K3: fold 19 slice partials + sigmoid (coalesced, high MLP)
// ---------------------------------------------------------------------------
__global__ void k3_sigmoid(float* __restrict__ out)
{
    int i = blockIdx.x * blockDim.x + threadIdx.x;   // 16384 threads
    float v = 0.0f;
    #pragma unroll
    for (int ks = 0; ks < KSLICES; ks++)
        v += g_gpart[ks * (BATCH * HID) + i];
    out[i] = 1.0f / (1.0f + expf(-v));
}

// ---------------------------------------------------------------------------
extern "C" void kernel_launch(void* const* d_in, const int* in_sizes, int n_in,
                              void* d_out, int out_size)
{
    const float* x    = (const float*)d_in[0];
    const int*   tc   = (const int*)  d_in[1];
    const int*   dc   = (const int*)  d_in[2];
    const void*  mask = (const void*) d_in[3];
    const float* h    = (const float*)d_in[4];
    const float* tw   = (const float*)d_in[5];
    const float* dw   = (const float*)d_in[6];
    const float* hw   = (const float*)d_in[7];
    float* out = (float*)d_out;

    k1_aggregate<<<BATCH, 256>>>(x, tc, dc, mask, h);
    dim3 g2(8, KSLICES);
    k2_gemm<<<g2, 256>>>(tw, dw, hw);
    k3_sigmoid<<<(BATCH * HID + 255) / 256, 256>>>(out);
}